// round 9
// baseline (speedup 1.0000x reference)
#include <cuda_runtime.h>
#include <cstdint>

#define CASCADES 3
#define GS3 16777216              // 256^3 cells per cascade
#define NCOORD 4194304            // GS3 / 4 coords per cascade
#define TOTAL_CELLS (CASCADES * GS3)          // 50331648
#define BITS_BYTES  (TOTAL_CELLS / 8)         // 6291456

// Scratch: per-cell winner = (coord_index + 1), 0 = no write. 3 x 64MB.
__device__ unsigned g_win[TOTAL_CELLS];

__device__ __forceinline__ unsigned p1b2(unsigned x) {
    x &= 0x3FFu;
    x = (x | (x << 16)) & 0x030000FFu;
    x = (x | (x << 8))  & 0x0300F00Fu;
    x = (x | (x << 4))  & 0x030C30C3u;
    x = (x | (x << 2))  & 0x09249249u;
    return x;
}
__device__ __forceinline__ unsigned morton(unsigned x, unsigned y, unsigned z) {
    return p1b2(x) | (p1b2(y) << 1) | (p1b2(z) << 2);
}

// One launch zeroes all three win regions (192MB).
__global__ void zero_all_k(uint4* __restrict__ p) {
    unsigned i = blockIdx.x * blockDim.x + threadIdx.x;
    if (i < TOTAL_CELLS / 4) p[i] = make_uint4(0u, 0u, 0u, 0u);
}

// One launch scatters all three cascades. 4 coords/thread.
// t in [0, 3*NCOORD/4); cascade = t >> 20 (NCOORD/4 == 2^20).
__global__ void scatter_all_k(const int4* __restrict__ coords4,
                              unsigned* __restrict__ win) {
    unsigned t = blockIdx.x * blockDim.x + threadIdx.x;
    if (t >= (CASCADES * NCOORD) / 4) return;
    unsigned c  = t >> 20;                  // cascade index
    unsigned tc = t & ((1u << 20) - 1u);    // coord-quad index within cascade

    int4 a = __ldcs(coords4 + 3u * t + 0u); // coords are contiguous across cascades
    int4 b = __ldcs(coords4 + 3u * t + 1u);
    int4 d = __ldcs(coords4 + 3u * t + 2u);

    unsigned* winc = win + ((size_t)c << 24);   // c * GS3
    unsigned base = 4u * tc;
    unsigned m0 = morton((unsigned)a.x, (unsigned)a.y, (unsigned)a.z);
    unsigned m1 = morton((unsigned)a.w, (unsigned)b.x, (unsigned)b.y);
    unsigned m2 = morton((unsigned)b.z, (unsigned)b.w, (unsigned)d.x);
    unsigned m3 = morton((unsigned)d.y, (unsigned)d.z, (unsigned)d.w);
    // last-write-wins: highest coord index wins (matches sequential scatter)
    atomicMax(winc + m0, base + 1u);
    atomicMax(winc + m1, base + 2u);
    atomicMax(winc + m2, base + 3u);
    atomicMax(winc + m3, base + 4u);
}

// One launch combines all three cascades. One byte (8 cells) per thread.
// t in [0, TOTAL_CELLS/8); cascade = t >> 21 (GS3/8 == 2^21).
template <int FLOATBITS>
__global__ void combine_all_k(const float* __restrict__ density,
                              const float* __restrict__ sigmas,
                              const unsigned* __restrict__ win,
                              float* __restrict__ out_grid,
                              uint8_t* __restrict__ out_bits_u8,
                              float* __restrict__ out_bits_f) {
    unsigned t = blockIdx.x * blockDim.x + threadIdx.x;
    if (t >= TOTAL_CELLS / 8) return;
    unsigned c = t >> 21;                               // cascade index
    const float* sigc = sigmas + ((size_t)c << 22);     // c * NCOORD

    uint4 w0 = ((const uint4*)win)[2 * t + 0];          // win/density/grid are
    uint4 w1 = ((const uint4*)win)[2 * t + 1];          // contiguous across cascades
    float4 d0 = ((const float4*)density)[2 * t + 0];
    float4 d1 = ((const float4*)density)[2 * t + 1];

    unsigned ws[8] = {w0.x, w0.y, w0.z, w0.w, w1.x, w1.y, w1.z, w1.w};
    float    dv[8] = {d0.x, d0.y, d0.z, d0.w, d1.x, d1.y, d1.z, d1.w};
    float    v[8];
    unsigned byte = 0u;

#pragma unroll
    for (int b = 0; b < 8; b++) {
        float val = dv[b];
        unsigned w = ws[b];
        if (w) {
            float s = __ldg(sigc + (w - 1u));     // DENSITY_SCALE == 1.0
            if (val >= 0.0f && s >= 0.0f)         // valid = old>=0 && new>=0
                val = fmaxf(0.95f * val, s);      // DECAY = 0.95
        }
        v[b] = val;
        if (val > 0.01f) byte |= (1u << b);       // DENSITY_THRESHOLD = 0.01
    }

    ((float4*)out_grid)[2 * t + 0] = make_float4(v[0], v[1], v[2], v[3]);
    ((float4*)out_grid)[2 * t + 1] = make_float4(v[4], v[5], v[6], v[7]);

    if (FLOATBITS) {
        out_bits_f[t] = (float)byte;
    } else {
        out_bits_u8[t] = (uint8_t)byte;
    }
}

extern "C" void kernel_launch(void* const* d_in, const int* in_sizes, int n_in,
                              void* d_out, int out_size) {
    const float* density = (const float*)d_in[0];   // [3, 256^3] f32
    const float* sigmas  = (const float*)d_in[1];   // [3, NCOORD] f32
    const int*   coords  = (const int*)d_in[2];     // [3, NCOORD, 3] i32

    unsigned* win = nullptr;
    cudaGetSymbolAddress((void**)&win, g_win);

    // Output layout: reference returns (new_grid f32, bitfield u8).
    const long long f32_elems = (long long)TOTAL_CELLS + (long long)BITS_BYTES;
    bool floatbits = ((long long)out_size == f32_elems);

    float*   out_grid = (float*)d_out;
    uint8_t* bits_u8  = (uint8_t*)d_out + (size_t)TOTAL_CELLS * 4;
    float*   bits_f   = (float*)d_out + (size_t)TOTAL_CELLS;

    const int ZB = (TOTAL_CELLS / 4) / 256;            // 49152 blocks
    const int SB = ((CASCADES * NCOORD) / 4) / 256;    // 12288 blocks
    const int CB = (TOTAL_CELLS / 8) / 256;            // 24576 blocks

    // Exactly 3 launches: zero -> scatter -> combine, each covering all
    // cascades. Fewer launch/tail boundaries than 9-launch versions; merged
    // grids amortize one tail over 3x the work.
    zero_all_k<<<ZB, 256>>>((uint4*)win);
    scatter_all_k<<<SB, 256>>>((const int4*)coords, win);
    if (floatbits) {
        combine_all_k<1><<<CB, 256>>>(density, sigmas, win,
                                      out_grid, nullptr, bits_f);
    } else {
        combine_all_k<0><<<CB, 256>>>(density, sigmas, win,
                                      out_grid, bits_u8, nullptr);
    }
}

// round 10
// speedup vs baseline: 1.1801x; 1.1801x over previous
#include <cuda_runtime.h>
#include <cstdint>

#define CASCADES 3
#define GS3 16777216              // 256^3 cells per cascade
#define NCOORD 4194304            // GS3 / 4 coords per cascade
#define TOTAL_CELLS (CASCADES * GS3)          // 50331648
#define BITS_BYTES  (TOTAL_CELLS / 8)         // 6291456

// Scratch: per-cell winner = (coord_index + 1), 0 = no write. 3 x 64MB
// regions, processed per-cascade so each 64MB region stays L2-resident
// through its zero -> scatter -> combine lifetime (R9 showed merging all
// three phases spills win to DRAM: 192MB > 126MB L2).
__device__ unsigned g_win[TOTAL_CELLS];

__device__ __forceinline__ unsigned p1b2(unsigned x) {
    x &= 0x3FFu;
    x = (x | (x << 16)) & 0x030000FFu;
    x = (x | (x << 8))  & 0x0300F00Fu;
    x = (x | (x << 4))  & 0x030C30C3u;
    x = (x | (x << 2))  & 0x09249249u;
    return x;
}
__device__ __forceinline__ unsigned morton(unsigned x, unsigned y, unsigned z) {
    return p1b2(x) | (p1b2(y) << 1) | (p1b2(z) << 2);
}

__global__ void zero_k(uint4* __restrict__ p, int n4) {
    int i = blockIdx.x * blockDim.x + threadIdx.x;
    if (i < n4) p[i] = make_uint4(0u, 0u, 0u, 0u);
}

// 4 coords per thread: 3 x int4 streaming loads, 4 fire-and-forget RED.MAX.
__global__ void scatter_k(const int4* __restrict__ coords4,
                          unsigned* __restrict__ win) {
    int t = blockIdx.x * blockDim.x + threadIdx.x;   // t < NCOORD/4
    if (t >= NCOORD / 4) return;
    int4 a = __ldcs(coords4 + 3 * t + 0);
    int4 b = __ldcs(coords4 + 3 * t + 1);
    int4 c = __ldcs(coords4 + 3 * t + 2);
    unsigned base = 4u * (unsigned)t;
    unsigned m0 = morton((unsigned)a.x, (unsigned)a.y, (unsigned)a.z);
    unsigned m1 = morton((unsigned)a.w, (unsigned)b.x, (unsigned)b.y);
    unsigned m2 = morton((unsigned)b.z, (unsigned)b.w, (unsigned)c.x);
    unsigned m3 = morton((unsigned)c.y, (unsigned)c.z, (unsigned)c.w);
    // last-write-wins: highest coord index wins (matches sequential scatter)
    atomicMax(win + m0, base + 1u);
    atomicMax(win + m1, base + 2u);
    atomicMax(win + m2, base + 3u);
    atomicMax(win + m3, base + 4u);
}

// Combine: 16 cells (2 output bytes) per thread. Doubled per-thread MLP vs
// the 8-cell version: 4 win loads + 4 density loads + up to 16 independent
// predicated sigma gathers in flight, hiding L2 gather latency.
template <int FLOATBITS>
__global__ void combine_k(const float* __restrict__ density,
                          const float* __restrict__ sigmas,
                          const unsigned* __restrict__ win,
                          float* __restrict__ out_grid,
                          uint8_t* __restrict__ out_bits_u8,
                          float* __restrict__ out_bits_f) {
    int t = blockIdx.x * blockDim.x + threadIdx.x;   // 16 cells per thread
    if (t >= GS3 / 16) return;

    uint4  w4[4];
    float4 d4[4];
#pragma unroll
    for (int q = 0; q < 4; q++) {
        w4[q] = ((const uint4*)win)[4 * t + q];
        d4[q] = ((const float4*)density)[4 * t + q];
    }

    unsigned ws[16];
    float    dv[16];
#pragma unroll
    for (int q = 0; q < 4; q++) {
        ws[4*q+0] = w4[q].x; ws[4*q+1] = w4[q].y;
        ws[4*q+2] = w4[q].z; ws[4*q+3] = w4[q].w;
        dv[4*q+0] = d4[q].x; dv[4*q+1] = d4[q].y;
        dv[4*q+2] = d4[q].z; dv[4*q+3] = d4[q].w;
    }

    // Issue all gathers up front (independent predicated loads -> high MLP).
    float sg[16];
#pragma unroll
    for (int b = 0; b < 16; b++)
        sg[b] = ws[b] ? __ldg(sigmas + (ws[b] - 1u)) : -1.0f;

    float v[16];
    unsigned bits = 0u;
#pragma unroll
    for (int b = 0; b < 16; b++) {
        float val = dv[b];
        if (ws[b]) {
            float s = sg[b];                      // DENSITY_SCALE == 1.0
            if (val >= 0.0f && s >= 0.0f)         // valid = old>=0 && new>=0
                val = fmaxf(0.95f * val, s);      // DECAY = 0.95
        }
        v[b] = val;
        if (val > 0.01f) bits |= (1u << b);       // DENSITY_THRESHOLD = 0.01
    }

#pragma unroll
    for (int q = 0; q < 4; q++)
        ((float4*)out_grid)[4 * t + q] =
            make_float4(v[4*q+0], v[4*q+1], v[4*q+2], v[4*q+3]);

    if (FLOATBITS) {
        ((float2*)out_bits_f)[t] =
            make_float2((float)(bits & 0xFFu), (float)(bits >> 8));
    } else {
        ((uint16_t*)out_bits_u8)[t] =
            (uint16_t)((bits & 0xFFu) | ((bits >> 8) << 8));
    }
}

extern "C" void kernel_launch(void* const* d_in, const int* in_sizes, int n_in,
                              void* d_out, int out_size) {
    const float* density = (const float*)d_in[0];   // [3, 256^3] f32
    const float* sigmas  = (const float*)d_in[1];   // [3, NCOORD] f32
    const int*   coords  = (const int*)d_in[2];     // [3, NCOORD, 3] i32

    unsigned* win = nullptr;
    cudaGetSymbolAddress((void**)&win, g_win);

    // Output layout: reference returns (new_grid f32, bitfield u8).
    const long long f32_elems = (long long)TOTAL_CELLS + (long long)BITS_BYTES;
    bool floatbits = ((long long)out_size == f32_elems);

    float*   out_grid = (float*)d_out;
    uint8_t* bits_u8  = (uint8_t*)d_out + (size_t)TOTAL_CELLS * 4;
    float*   bits_f   = (float*)d_out + (size_t)TOTAL_CELLS;

    const int ZB = (GS3 / 4) / 256;      // zero blocks
    const int SB = (NCOORD / 4) / 256;   // scatter blocks
    const int CB = (GS3 / 16) / 256;     // combine blocks (16 cells/thread)

    // Per-cascade serial pipeline (best-known structure: R1, 256.6us).
    for (int c = 0; c < CASCADES; c++) {
        unsigned*    winc = win + (size_t)c * GS3;
        const float* denc = density + (size_t)c * GS3;
        const float* sigc = sigmas + (size_t)c * NCOORD;
        const int4*  crdc = (const int4*)(coords + (size_t)c * NCOORD * 3);

        zero_k<<<ZB, 256>>>((uint4*)winc, GS3 / 4);
        scatter_k<<<SB, 256>>>(crdc, winc);
        if (floatbits) {
            combine_k<1><<<CB, 256>>>(denc, sigc, winc,
                                      out_grid + (size_t)c * GS3,
                                      nullptr,
                                      bits_f + (size_t)c * (GS3 / 8));
        } else {
            combine_k<0><<<CB, 256>>>(denc, sigc, winc,
                                      out_grid + (size_t)c * GS3,
                                      bits_u8 + (size_t)c * (GS3 / 8),
                                      nullptr);
        }
    }
}